// round 6
// baseline (speedup 1.0000x reference)
#include <cuda_runtime.h>
#include <math.h>
#include <stdint.h>

#define HID   768
#define SEQ   4096
#define BATCH 4
#define MTOT  (BATCH*SEQ)   // 16384

#define BM 128
#define BN 128
#define BK 16
#define NSTG 4
#define PADA 20
#define PADB 136

#define ABT_STAGE 20480
#define ABT_BOFF  10240
#define ABT_SMEM  (NSTG*ABT_STAGE)   // 81920
#define ABN_STAGE 18944
#define ABN_BOFF  10240
#define ABN_SMEM  (NSTG*ABN_STAGE)   // 75776

// ---------------- scratch ----------------
__device__ float g_q[(size_t)MTOT * HID];
__device__ float g_k[(size_t)MTOT * HID];
__device__ float g_v[(size_t)MTOT * HID];
__device__ float g_s[(size_t)BATCH * SEQ * SEQ];
__device__ float g_x[(size_t)MTOT * HID];          // tf32-rounded x
__device__ float g_wq[HID * HID];                  // tf32-rounded weights
__device__ float g_wk[HID * HID];
__device__ float g_wv[HID * HID];

// ---------------- helpers ----------------
__device__ __forceinline__ uint32_t smem_u32(const void* p) {
    uint32_t a;
    asm("{ .reg .u64 t; cvta.to.shared.u64 t, %1; cvt.u32.u64 %0, t; }" : "=r"(a) : "l"(p));
    return a;
}
__device__ __forceinline__ void cp16(uint32_t dst, const void* src) {
    asm volatile("cp.async.cg.shared.global [%0], [%1], 16;" :: "r"(dst), "l"(src));
}
__device__ __forceinline__ void cp_commit() {
    asm volatile("cp.async.commit_group;" ::: "memory");
}
template<int N> __device__ __forceinline__ void cp_wait() {
    asm volatile("cp.async.wait_group %0;" :: "n"(N) : "memory");
}
__device__ __forceinline__ unsigned f2tf(float x) {
    unsigned y; asm("cvt.rna.tf32.f32 %0, %1;" : "=r"(y) : "f"(x)); return y;
}
__device__ __forceinline__ float tf32r(float x) { return __uint_as_float(f2tf(x)); }
__device__ __forceinline__ void mma8(float* c, const unsigned* a, unsigned b0, unsigned b1) {
    asm volatile(
        "mma.sync.aligned.m16n8k8.row.col.f32.tf32.tf32.f32 "
        "{%0,%1,%2,%3}, {%4,%5,%6,%7}, {%8,%9}, {%0,%1,%2,%3};"
        : "+f"(c[0]), "+f"(c[1]), "+f"(c[2]), "+f"(c[3])
        : "r"(a[0]), "r"(a[1]), "r"(a[2]), "r"(a[3]), "r"(b0), "r"(b1));
}

// ---------------- compute cores (inputs pre-rounded; no cvt) ----------------
__device__ __forceinline__ void compute_stage(
    const float* sA, const float* sB, float acc[4][4][4],
    int wm, int wn, int gid, int tig)
{
#pragma unroll
    for (int kk = 0; kk < BK; kk += 8) {
        unsigned a[4][4], b[4][2];
#pragma unroll
        for (int mi = 0; mi < 4; mi++) {
            const float* ap = sA + (wm + mi * 16 + gid) * PADA + kk + tig;
            a[mi][0] = __float_as_uint(ap[0]);
            a[mi][1] = __float_as_uint(ap[8 * PADA]);
            a[mi][2] = __float_as_uint(ap[4]);
            a[mi][3] = __float_as_uint(ap[8 * PADA + 4]);
        }
#pragma unroll
        for (int ni = 0; ni < 4; ni++) {
            const float* bp = sB + (wn + ni * 8 + gid) * PADA + kk + tig;
            b[ni][0] = __float_as_uint(bp[0]);
            b[ni][1] = __float_as_uint(bp[4]);
        }
#pragma unroll
        for (int mi = 0; mi < 4; mi++)
#pragma unroll
            for (int ni = 0; ni < 4; ni++)
                mma8(acc[mi][ni], a[mi], b[ni][0], b[ni][1]);
    }
}
__device__ __forceinline__ void compute_stage_bn(
    const float* sA, const float* sB, float acc[4][4][4],
    int wm, int wn, int gid, int tig)
{
#pragma unroll
    for (int kk = 0; kk < BK; kk += 8) {
        unsigned a[4][4], b[4][2];
#pragma unroll
        for (int mi = 0; mi < 4; mi++) {
            const float* ap = sA + (wm + mi * 16 + gid) * PADA + kk + tig;
            a[mi][0] = __float_as_uint(ap[0]);
            a[mi][1] = __float_as_uint(ap[8 * PADA]);
            a[mi][2] = __float_as_uint(ap[4]);
            a[mi][3] = __float_as_uint(ap[8 * PADA + 4]);
        }
#pragma unroll
        for (int ni = 0; ni < 4; ni++) {
            const float* bp = sB + (kk + tig) * PADB + wn + ni * 8 + gid;
            b[ni][0] = __float_as_uint(bp[0]);
            b[ni][1] = __float_as_uint(bp[4 * PADB]);
        }
#pragma unroll
        for (int mi = 0; mi < 4; mi++)
#pragma unroll
            for (int ni = 0; ni < 4; ni++)
                mma8(acc[mi][ni], a[mi], b[ni][0], b[ni][1]);
    }
}

// round_out: round stored values to tf32 (for q/k/v, consumed by later GEMMs)
__device__ __forceinline__ void store_epilogue(
    float* __restrict__ C, const float* __restrict__ bias,
    float acc[4][4][4], int m0, int n0, int ldc, float alpha,
    int wm, int wn, int gid, int tig, bool round_out)
{
#pragma unroll
    for (int mi = 0; mi < 4; mi++) {
        int r0 = m0 + wm + mi * 16 + gid;
#pragma unroll
        for (int ni = 0; ni < 4; ni++) {
            int c0 = n0 + wn + ni * 8 + 2 * tig;
            float bb0 = bias ? bias[c0]     : 0.f;
            float bb1 = bias ? bias[c0 + 1] : 0.f;
            float2 v0 = make_float2(acc[mi][ni][0] * alpha + bb0,
                                    acc[mi][ni][1] * alpha + bb1);
            float2 v1 = make_float2(acc[mi][ni][2] * alpha + bb0,
                                    acc[mi][ni][3] * alpha + bb1);
            if (round_out) {
                v0.x = tf32r(v0.x); v0.y = tf32r(v0.y);
                v1.x = tf32r(v1.x); v1.y = tf32r(v1.y);
            }
            *(float2*)(C + (size_t)r0 * ldc + c0)       = v0;
            *(float2*)(C + (size_t)(r0 + 8) * ldc + c0) = v1;
        }
    }
}

// ---------------- C = alpha * A * Bt^T (+bias), cp.async 4-stage ----------------
__device__ __forceinline__ void gemm_abt_body(
    const float* __restrict__ A, const float* __restrict__ Bt,
    float* __restrict__ C, const float* __restrict__ bias,
    int K, int lda, int ldb, int ldc, float alpha, bool round_out)
{
    extern __shared__ char smem[];
    const uint32_t sb = smem_u32(smem);

    const int tid  = threadIdx.x;
    const int lane = tid & 31;
    const int warp = tid >> 5;
    const int gid  = lane >> 2;
    const int tig  = lane & 3;
    const int wm   = (warp & 1) * 64;
    const int wn   = (warp >> 1) * 32;
    const int m0 = blockIdx.x * BM, n0 = blockIdx.y * BN;

    float acc[4][4][4];
#pragma unroll
    for (int i = 0; i < 4; i++)
#pragma unroll
        for (int j = 0; j < 4; j++)
#pragma unroll
            for (int l = 0; l < 4; l++) acc[i][j][l] = 0.f;

    const int KT = K / BK;
    const int r  = tid >> 2;
    const int ch = tid & 3;

#pragma unroll
    for (int s = 0; s < NSTG - 1; s++) {
        const int k0 = s * BK;
        const uint32_t st = sb + s * ABT_STAGE;
#pragma unroll
        for (int i = 0; i < 2; i++) {
            int rr = r + i * 64;
            cp16(st + rr * 80 + ch * 16, A  + (size_t)(m0 + rr) * lda + k0 + ch * 4);
            cp16(st + ABT_BOFF + rr * 80 + ch * 16, Bt + (size_t)(n0 + rr) * ldb + k0 + ch * 4);
        }
        cp_commit();
    }

    for (int kt = 0; kt < KT; kt++) {
        if (kt + NSTG - 1 < KT) {
            const int k0 = (kt + NSTG - 1) * BK;
            const uint32_t st = sb + ((kt + NSTG - 1) % NSTG) * ABT_STAGE;
#pragma unroll
            for (int i = 0; i < 2; i++) {
                int rr = r + i * 64;
                cp16(st + rr * 80 + ch * 16, A  + (size_t)(m0 + rr) * lda + k0 + ch * 4);
                cp16(st + ABT_BOFF + rr * 80 + ch * 16, Bt + (size_t)(n0 + rr) * ldb + k0 + ch * 4);
            }
            cp_commit();
            cp_wait<NSTG - 1>();
        } else {
            cp_wait<0>();
        }
        __syncthreads();
        const float* sA = (const float*)(smem + (kt % NSTG) * ABT_STAGE);
        compute_stage(sA, sA + ABT_BOFF / 4, acc, wm, wn, gid, tig);
        __syncthreads();
    }
    store_epilogue(C, bias, acc, m0, n0, ldc, alpha, wm, wn, gid, tig, round_out);
}

// ---------------- C = A * B (B row-major [K][N]), cp.async 4-stage ----------------
__device__ __forceinline__ void gemm_abn_body(
    const float* __restrict__ A, const float* __restrict__ B,
    float* __restrict__ C, int K, int lda, int ldb, int ldc)
{
    extern __shared__ char smem[];
    const uint32_t sb = smem_u32(smem);

    const int tid  = threadIdx.x;
    const int lane = tid & 31;
    const int warp = tid >> 5;
    const int gid  = lane >> 2;
    const int tig  = lane & 3;
    const int wm   = (warp & 1) * 64;
    const int wn   = (warp >> 1) * 32;
    const int m0 = blockIdx.x * BM, n0 = blockIdx.y * BN;

    float acc[4][4][4];
#pragma unroll
    for (int i = 0; i < 4; i++)
#pragma unroll
        for (int j = 0; j < 4; j++)
#pragma unroll
            for (int l = 0; l < 4; l++) acc[i][j][l] = 0.f;

    const int KT = K / BK;
    const int r  = tid >> 2;
    const int ch = tid & 3;
    const int br = tid >> 5;
    const int bc = tid & 31;

#pragma unroll
    for (int s = 0; s < NSTG - 1; s++) {
        const int k0 = s * BK;
        const uint32_t st = sb + s * ABN_STAGE;
#pragma unroll
        for (int i = 0; i < 2; i++) {
            int rr = r + i * 64;
            cp16(st + rr * 80 + ch * 16, A + (size_t)(m0 + rr) * lda + k0 + ch * 4);
        }
#pragma unroll
        for (int i = 0; i < 2; i++) {
            int kr = br + i * 8;
            cp16(st + ABN_BOFF + kr * 544 + bc * 16, B + (size_t)(k0 + kr) * ldb + n0 + bc * 4);
        }
        cp_commit();
    }

    for (int kt = 0; kt < KT; kt++) {
        if (kt + NSTG - 1 < KT) {
            const int k0 = (kt + NSTG - 1) * BK;
            const uint32_t st = sb + ((kt + NSTG - 1) % NSTG) * ABN_STAGE;
#pragma unroll
            for (int i = 0; i < 2; i++) {
                int rr = r + i * 64;
                cp16(st + rr * 80 + ch * 16, A + (size_t)(m0 + rr) * lda + k0 + ch * 4);
            }
#pragma unroll
            for (int i = 0; i < 2; i++) {
                int kr = br + i * 8;
                cp16(st + ABN_BOFF + kr * 544 + bc * 16, B + (size_t)(k0 + kr) * ldb + n0 + bc * 4);
            }
            cp_commit();
            cp_wait<NSTG - 1>();
        } else {
            cp_wait<0>();
        }
        __syncthreads();
        const float* sA = (const float*)(smem + (kt % NSTG) * ABN_STAGE);
        compute_stage_bn(sA, sA + ABN_BOFF / 4, acc, wm, wn, gid, tig);
        __syncthreads();
    }
    store_epilogue(C, nullptr, acc, m0, n0, ldc, 1.0f, wm, wn, gid, tig, false);
}

// ---------------- round-to-tf32 prepass ----------------
__global__ void __launch_bounds__(256) round_kernel(const float* __restrict__ src,
                                                    float* __restrict__ dst, int n4)
{
    int i = blockIdx.x * 256 + threadIdx.x;
    int stride = gridDim.x * 256;
    for (; i < n4; i += stride) {
        float4 v = ((const float4*)src)[i];
        v.x = tf32r(v.x); v.y = tf32r(v.y); v.z = tf32r(v.z); v.w = tf32r(v.w);
        ((float4*)dst)[i] = v;
    }
}

// ---------------- kernels ----------------
__global__ void __launch_bounds__(256, 2) qkv_kernel(
    const float* __restrict__ bq, const float* __restrict__ bk,
    const float* __restrict__ bv)
{
    int z = blockIdx.z;
    const float* W = (z == 0) ? g_wq : (z == 1) ? g_wk : g_wv;
    const float* b = (z == 0) ? bq : (z == 1) ? bk : bv;
    float* out     = (z == 0) ? g_q : (z == 1) ? g_k : g_v;
    gemm_abt_body(g_x, W, out, b, HID, HID, HID, HID, 1.0f, true);
}

__global__ void __launch_bounds__(256, 2) scores_kernel()
{
    int z = blockIdx.z;
    gemm_abt_body(g_q + (size_t)z * SEQ * HID,
                  g_k + (size_t)z * SEQ * HID,
                  g_s + (size_t)z * SEQ * SEQ,
                  nullptr, HID, HID, HID, SEQ, 0.036084391824351615f, false);
}

__global__ void __launch_bounds__(256, 2) av_kernel(float* __restrict__ out)
{
    int z = blockIdx.z;
    gemm_abn_body(g_s + (size_t)z * SEQ * SEQ,
                  g_v + (size_t)z * SEQ * HID,
                  out + (size_t)z * SEQ * HID,
                  SEQ, SEQ, HID, HID);
}

__global__ void __launch_bounds__(256) softmax_kernel()
{
    __shared__ float red[8];
    const int row = blockIdx.x;
    float* p = g_s + (size_t)row * SEQ;
    const int tid = threadIdx.x;

    float v[16];
    float mx = -__int_as_float(0x7f800000);
#pragma unroll
    for (int i = 0; i < 4; i++) {
        float4 t = *(const float4*)(p + (size_t)(tid + i * 256) * 4);
        v[i*4+0] = t.x; v[i*4+1] = t.y; v[i*4+2] = t.z; v[i*4+3] = t.w;
        mx = fmaxf(mx, fmaxf(fmaxf(t.x, t.y), fmaxf(t.z, t.w)));
    }
#pragma unroll
    for (int o = 16; o; o >>= 1) mx = fmaxf(mx, __shfl_xor_sync(0xffffffffu, mx, o));
    if ((tid & 31) == 0) red[tid >> 5] = mx;
    __syncthreads();
    float bm = red[0];
#pragma unroll
    for (int i = 1; i < 8; i++) bm = fmaxf(bm, red[i]);

    float sum = 0.f;
#pragma unroll
    for (int i = 0; i < 16; i++) { v[i] = __expf(v[i] - bm); sum += v[i]; }
#pragma unroll
    for (int o = 16; o; o >>= 1) sum += __shfl_xor_sync(0xffffffffu, sum, o);
    __syncthreads();
    if ((tid & 31) == 0) red[tid >> 5] = sum;
    __syncthreads();
    float bs = 0.f;
#pragma unroll
    for (int i = 0; i < 8; i++) bs += red[i];
    float inv = 1.0f / bs;

    // store probabilities rounded to tf32 so av_kernel needs no cvt
#pragma unroll
    for (int i = 0; i < 4; i++) {
        float4 t = make_float4(tf32r(v[i*4+0]*inv), tf32r(v[i*4+1]*inv),
                               tf32r(v[i*4+2]*inv), tf32r(v[i*4+3]*inv));
        *(float4*)(p + (size_t)(tid + i * 256) * 4) = t;
    }
}

// ---------------- launch ----------------
extern "C" void kernel_launch(void* const* d_in, const int* in_sizes, int n_in,
                              void* d_out, int out_size)
{
    const float* x  = (const float*)d_in[0];
    const float* Wq = (const float*)d_in[1];
    const float* bq = (const float*)d_in[2];
    const float* Wk = (const float*)d_in[3];
    const float* bk = (const float*)d_in[4];
    const float* Wv = (const float*)d_in[5];
    const float* bv = (const float*)d_in[6];
    float* out = (float*)d_out;

    cudaFuncSetAttribute(qkv_kernel,    cudaFuncAttributeMaxDynamicSharedMemorySize, ABT_SMEM);
    cudaFuncSetAttribute(scores_kernel, cudaFuncAttributeMaxDynamicSharedMemorySize, ABT_SMEM);
    cudaFuncSetAttribute(av_kernel,     cudaFuncAttributeMaxDynamicSharedMemorySize, ABN_SMEM);

    float *gx, *gwq, *gwk, *gwv;
    cudaGetSymbolAddress((void**)&gx,  g_x);
    cudaGetSymbolAddress((void**)&gwq, g_wq);
    cudaGetSymbolAddress((void**)&gwk, g_wk);
    cudaGetSymbolAddress((void**)&gwv, g_wv);

    dim3 blk(256);
    round_kernel<<<512, blk>>>(x,  gx,  MTOT * HID / 4);
    round_kernel<<<64,  blk>>>(Wq, gwq, HID * HID / 4);
    round_kernel<<<64,  blk>>>(Wk, gwk, HID * HID / 4);
    round_kernel<<<64,  blk>>>(Wv, gwv, HID * HID / 4);
    qkv_kernel<<<dim3(MTOT / BM, HID / BN, 3), blk, ABT_SMEM>>>(bq, bk, bv);
    scores_kernel<<<dim3(SEQ / BM, SEQ / BN, BATCH), blk, ABT_SMEM>>>();
    softmax_kernel<<<dim3(MTOT), blk>>>();
    av_kernel<<<dim3(SEQ / BM, HID / BN, BATCH), blk, ABN_SMEM>>>(out);
}

// round 7
// speedup vs baseline: 1.5880x; 1.5880x over previous
#include <cuda_runtime.h>
#include <cuda_fp16.h>
#include <math.h>
#include <stdint.h>

#define HID   768
#define SEQ   4096
#define BATCH 4
#define MTOT  (BATCH*SEQ)   // 16384

#define BM 128
#define BN 128
#define BKH 32               // halves per stage (64B data per row)
#define NSTG 4
#define PADH 40              // halves per smem row (32 data + 8 pad) = 80B

#define H_STAGE 20480        // A 128*80 + B 128*80
#define H_BOFF  10240
#define H_SMEM  (NSTG*H_STAGE)   // 81920

// ---------------- scratch ----------------
__device__ __half g_xh[(size_t)MTOT * HID];
__device__ __half g_wqh[HID * HID];
__device__ __half g_wkh[HID * HID];
__device__ __half g_wvh[HID * HID];
__device__ __half g_q[(size_t)MTOT * HID];
__device__ __half g_k[(size_t)MTOT * HID];
__device__ __half g_v[(size_t)MTOT * HID];
__device__ __half g_vt[(size_t)MTOT * HID];            // [b][d][s]
__device__ float  g_s[(size_t)BATCH * SEQ * SEQ];      // fp32 logits
__device__ __half g_p[(size_t)BATCH * SEQ * SEQ];      // fp16 probs

// ---------------- helpers ----------------
__device__ __forceinline__ uint32_t smem_u32(const void* p) {
    uint32_t a;
    asm("{ .reg .u64 t; cvta.to.shared.u64 t, %1; cvt.u32.u64 %0, t; }" : "=r"(a) : "l"(p));
    return a;
}
__device__ __forceinline__ void cp16(uint32_t dst, const void* src) {
    asm volatile("cp.async.cg.shared.global [%0], [%1], 16;" :: "r"(dst), "l"(src));
}
__device__ __forceinline__ void cp_commit() {
    asm volatile("cp.async.commit_group;" ::: "memory");
}
template<int N> __device__ __forceinline__ void cp_wait() {
    asm volatile("cp.async.wait_group %0;" :: "n"(N) : "memory");
}
__device__ __forceinline__ void mma16(float* c, const unsigned* a, unsigned b0, unsigned b1) {
    asm volatile(
        "mma.sync.aligned.m16n8k16.row.col.f32.f16.f16.f32 "
        "{%0,%1,%2,%3}, {%4,%5,%6,%7}, {%8,%9}, {%0,%1,%2,%3};"
        : "+f"(c[0]), "+f"(c[1]), "+f"(c[2]), "+f"(c[3])
        : "r"(a[0]), "r"(a[1]), "r"(a[2]), "r"(a[3]), "r"(b0), "r"(b1));
}

// ---------------- fp16 compute core: warp 64x32, BK=32 (two k16 groups) ----------------
__device__ __forceinline__ void compute_stage_h(
    const __half* sA, const __half* sB, float acc[4][4][4],
    int wm, int wn, int gid, int tig)
{
#pragma unroll
    for (int kg = 0; kg < BKH; kg += 16) {
        unsigned a[4][4], b[4][2];
#pragma unroll
        for (int mi = 0; mi < 4; mi++) {
            const __half* ap = sA + (wm + mi * 16 + gid) * PADH + kg + tig * 2;
            a[mi][0] = *(const uint32_t*)(ap);
            a[mi][1] = *(const uint32_t*)(ap + 8 * PADH);
            a[mi][2] = *(const uint32_t*)(ap + 8);
            a[mi][3] = *(const uint32_t*)(ap + 8 * PADH + 8);
        }
#pragma unroll
        for (int ni = 0; ni < 4; ni++) {
            const __half* bp = sB + (wn + ni * 8 + gid) * PADH + kg + tig * 2;
            b[ni][0] = *(const uint32_t*)(bp);
            b[ni][1] = *(const uint32_t*)(bp + 8);
        }
#pragma unroll
        for (int mi = 0; mi < 4; mi++)
#pragma unroll
            for (int ni = 0; ni < 4; ni++)
                mma16(acc[mi][ni], a[mi], b[ni][0], b[ni][1]);
    }
}

// ---------------- fp16 ABT GEMM: D = alpha*A*Bt^T (+bias); out fp32 or fp16 ----------------
// OutMode: 0 = fp32 store, 1 = fp16 store (with bias)
template<int OutMode>
__device__ __forceinline__ void gemm_h_body(
    const __half* __restrict__ A, const __half* __restrict__ Bt,
    void* __restrict__ Cv, const float* __restrict__ bias,
    int K, int lda, int ldb, int ldc, float alpha)
{
    extern __shared__ char smem[];
    const uint32_t sb = smem_u32(smem);

    const int tid  = threadIdx.x;
    const int lane = tid & 31;
    const int warp = tid >> 5;
    const int gid  = lane >> 2;
    const int tig  = lane & 3;
    const int wm   = (warp & 1) * 64;
    const int wn   = (warp >> 1) * 32;
    const int m0 = blockIdx.x * BM, n0 = blockIdx.y * BN;

    float acc[4][4][4];
#pragma unroll
    for (int i = 0; i < 4; i++)
#pragma unroll
        for (int j = 0; j < 4; j++)
#pragma unroll
            for (int l = 0; l < 4; l++) acc[i][j][l] = 0.f;

    const int KT = K / BKH;
    const int r  = tid >> 1;            // 0..127 row
    const int c2 = (tid & 1) * 2;       // chunk pair: chunks c2, c2+1 (16B each, 8 halves)

    // prologue: stages 0..NSTG-2
#pragma unroll
    for (int s = 0; s < NSTG - 1; s++) {
        const int k0 = s * BKH;
        const uint32_t st = sb + s * H_STAGE;
#pragma unroll
        for (int c = 0; c < 2; c++) {
            cp16(st + r * 80 + (c2 + c) * 16,          A  + (size_t)(m0 + r) * lda + k0 + (c2 + c) * 8);
            cp16(st + H_BOFF + r * 80 + (c2 + c) * 16, Bt + (size_t)(n0 + r) * ldb + k0 + (c2 + c) * 8);
        }
        cp_commit();
    }

    for (int kt = 0; kt < KT; kt++) {
        cp_wait<NSTG - 2>();          // stage kt complete
        __syncthreads();              // all warps done with stage kt-1's buffer
        if (kt + NSTG - 1 < KT) {
            const int k0 = (kt + NSTG - 1) * BKH;
            const uint32_t st = sb + ((kt + NSTG - 1) % NSTG) * H_STAGE;
#pragma unroll
            for (int c = 0; c < 2; c++) {
                cp16(st + r * 80 + (c2 + c) * 16,          A  + (size_t)(m0 + r) * lda + k0 + (c2 + c) * 8);
                cp16(st + H_BOFF + r * 80 + (c2 + c) * 16, Bt + (size_t)(n0 + r) * ldb + k0 + (c2 + c) * 8);
            }
        }
        cp_commit();                  // keep group cadence (empty group in tail)
        const __half* sA = (const __half*)(smem + (kt % NSTG) * H_STAGE);
        compute_stage_h(sA, sA + H_BOFF / 2, acc, wm, wn, gid, tig);
    }

    // epilogue
#pragma unroll
    for (int mi = 0; mi < 4; mi++) {
        int r0 = m0 + wm + mi * 16 + gid;
#pragma unroll
        for (int ni = 0; ni < 4; ni++) {
            int c0 = n0 + wn + ni * 8 + 2 * tig;
            float bb0 = bias ? bias[c0]     : 0.f;
            float bb1 = bias ? bias[c0 + 1] : 0.f;
            float v00 = acc[mi][ni][0] * alpha + bb0;
            float v01 = acc[mi][ni][1] * alpha + bb1;
            float v10 = acc[mi][ni][2] * alpha + bb0;
            float v11 = acc[mi][ni][3] * alpha + bb1;
            if (OutMode == 0) {
                float* C = (float*)Cv;
                *(float2*)(C + (size_t)r0 * ldc + c0)       = make_float2(v00, v01);
                *(float2*)(C + (size_t)(r0 + 8) * ldc + c0) = make_float2(v10, v11);
            } else {
                __half* C = (__half*)Cv;
                *(__half2*)(C + (size_t)r0 * ldc + c0)       = __floats2half2_rn(v00, v01);
                *(__half2*)(C + (size_t)(r0 + 8) * ldc + c0) = __floats2half2_rn(v10, v11);
            }
        }
    }
}

// ---------------- kernels ----------------
__global__ void __launch_bounds__(256, 2) qkv_kernel(
    const float* __restrict__ bq, const float* __restrict__ bk,
    const float* __restrict__ bv)
{
    int z = blockIdx.z;
    const __half* W = (z == 0) ? g_wqh : (z == 1) ? g_wkh : g_wvh;
    const float*  b = (z == 0) ? bq : (z == 1) ? bk : bv;
    __half* out     = (z == 0) ? g_q : (z == 1) ? g_k : g_v;
    gemm_h_body<1>(g_xh, W, out, b, HID, HID, HID, HID, 1.0f);
}

__global__ void __launch_bounds__(256, 2) scores_kernel()
{
    int z = blockIdx.z;
    gemm_h_body<0>(g_q + (size_t)z * SEQ * HID,
                   g_k + (size_t)z * SEQ * HID,
                   g_s + (size_t)z * SEQ * SEQ,
                   nullptr, HID, HID, HID, SEQ, 0.036084391824351615f);
}

__global__ void __launch_bounds__(256, 2) av_kernel(float* __restrict__ out)
{
    int z = blockIdx.z;
    gemm_h_body<0>(g_p  + (size_t)z * SEQ * SEQ,
                   g_vt + (size_t)z * SEQ * HID,
                   out  + (size_t)z * SEQ * HID,
                   nullptr, SEQ, SEQ, SEQ, HID, 1.0f);
}

__global__ void __launch_bounds__(256) softmax_kernel()
{
    __shared__ float red[8];
    const int row = blockIdx.x;
    const float* p = g_s + (size_t)row * SEQ;
    __half* po = g_p + (size_t)row * SEQ;
    const int tid = threadIdx.x;

    float v[16];
    float mx = -__int_as_float(0x7f800000);
#pragma unroll
    for (int i = 0; i < 4; i++) {
        float4 t = *(const float4*)(p + (size_t)(tid + i * 256) * 4);
        v[i*4+0] = t.x; v[i*4+1] = t.y; v[i*4+2] = t.z; v[i*4+3] = t.w;
        mx = fmaxf(mx, fmaxf(fmaxf(t.x, t.y), fmaxf(t.z, t.w)));
    }
#pragma unroll
    for (int o = 16; o; o >>= 1) mx = fmaxf(mx, __shfl_xor_sync(0xffffffffu, mx, o));
    if ((tid & 31) == 0) red[tid >> 5] = mx;
    __syncthreads();
    float bm = red[0];
#pragma unroll
    for (int i = 1; i < 8; i++) bm = fmaxf(bm, red[i]);

    float sum = 0.f;
#pragma unroll
    for (int i = 0; i < 16; i++) { v[i] = __expf(v[i] - bm); sum += v[i]; }
#pragma unroll
    for (int o = 16; o; o >>= 1) sum += __shfl_xor_sync(0xffffffffu, sum, o);
    __syncthreads();
    if ((tid & 31) == 0) red[tid >> 5] = sum;
    __syncthreads();
    float bs = 0.f;
#pragma unroll
    for (int i = 0; i < 8; i++) bs += red[i];
    float inv = 1.0f / bs;

#pragma unroll
    for (int i = 0; i < 4; i++) {
        int base = (tid + i * 256) * 4;
        *(__half2*)(po + base)     = __floats2half2_rn(v[i*4+0] * inv, v[i*4+1] * inv);
        *(__half2*)(po + base + 2) = __floats2half2_rn(v[i*4+2] * inv, v[i*4+3] * inv);
    }
}

// fp32 -> fp16 conversion prepass
__global__ void __launch_bounds__(256) f2h_kernel(const float* __restrict__ src,
                                                  __half* __restrict__ dst, int n4)
{
    int i = blockIdx.x * 256 + threadIdx.x;
    int stride = gridDim.x * 256;
    for (; i < n4; i += stride) {
        float4 v = ((const float4*)src)[i];
        ((__half2*)dst)[2*i]   = __floats2half2_rn(v.x, v.y);
        ((__half2*)dst)[2*i+1] = __floats2half2_rn(v.z, v.w);
    }
}

// V transpose (fp16): g_vt[b][d][s] = g_v[b][s][d]
__global__ void __launch_bounds__(256) vtrans_kernel()
{
    __shared__ __half t[32][33];
    const int z = blockIdx.z;
    const int s0 = blockIdx.x * 32;
    const int d0 = blockIdx.y * 32;
    const int tx = threadIdx.x & 31;
    const int ty = threadIdx.x >> 5;
    const __half* src = g_v  + (size_t)z * SEQ * HID;
    __half*       dst = g_vt + (size_t)z * SEQ * HID;
#pragma unroll
    for (int j = 0; j < 4; j++)
        t[ty + j * 8][tx] = src[(size_t)(s0 + ty + j * 8) * HID + d0 + tx];
    __syncthreads();
#pragma unroll
    for (int j = 0; j < 4; j++)
        dst[(size_t)(d0 + ty + j * 8) * SEQ + s0 + tx] = t[tx][ty + j * 8];
}

// ---------------- launch ----------------
extern "C" void kernel_launch(void* const* d_in, const int* in_sizes, int n_in,
                              void* d_out, int out_size)
{
    const float* x  = (const float*)d_in[0];
    const float* Wq = (const float*)d_in[1];
    const float* bq = (const float*)d_in[2];
    const float* Wk = (const float*)d_in[3];
    const float* bk = (const float*)d_in[4];
    const float* Wv = (const float*)d_in[5];
    const float* bv = (const float*)d_in[6];
    float* out = (float*)d_out;

    cudaFuncSetAttribute(qkv_kernel,    cudaFuncAttributeMaxDynamicSharedMemorySize, H_SMEM);
    cudaFuncSetAttribute(scores_kernel, cudaFuncAttributeMaxDynamicSharedMemorySize, H_SMEM);
    cudaFuncSetAttribute(av_kernel,     cudaFuncAttributeMaxDynamicSharedMemorySize, H_SMEM);

    __half *gxh, *gwqh, *gwkh, *gwvh;
    cudaGetSymbolAddress((void**)&gxh,  g_xh);
    cudaGetSymbolAddress((void**)&gwqh, g_wqh);
    cudaGetSymbolAddress((void**)&gwkh, g_wkh);
    cudaGetSymbolAddress((void**)&gwvh, g_wvh);

    dim3 blk(256);
    f2h_kernel<<<1024, blk>>>(x,  gxh,  MTOT * HID / 4);
    f2h_kernel<<<128,  blk>>>(Wq, gwqh, HID * HID / 4);
    f2h_kernel<<<128,  blk>>>(Wk, gwkh, HID * HID / 4);
    f2h_kernel<<<128,  blk>>>(Wv, gwvh, HID * HID / 4);
    qkv_kernel<<<dim3(MTOT / BM, HID / BN, 3), blk, H_SMEM>>>(bq, bk, bv);
    vtrans_kernel<<<dim3(SEQ / 32, HID / 32, BATCH), blk>>>();
    scores_kernel<<<dim3(SEQ / BM, SEQ / BN, BATCH), blk, H_SMEM>>>();
    softmax_kernel<<<dim3(MTOT), blk>>>();
    av_kernel<<<dim3(SEQ / BM, HID / BN, BATCH), blk, H_SMEM>>>(out);
}